// round 12
// baseline (speedup 1.0000x reference)
#include <cuda_runtime.h>
#include <cuda_fp16.h>
#include <math.h>
#include <stdint.h>

// ---------------- problem constants ----------------
#define B_TOTAL   131072
#define DH        32
#define TWO_PI_F  6.283185307179586f
#define NSLOTS    296          // 2 CTAs x 148 SMs, single persistent wave
#define NJOBS_TOT 4096         // 1024 row-tiles x 4 col-quarters

// ---------------- device scratch (static, no alloc) ----------------
__device__ __half g_xhi[(size_t)B_TOTAL * 64];
__device__ __half g_xlo[(size_t)B_TOTAL * 64];
__device__ __half g_hhi[(size_t)B_TOTAL * 512];
__device__ __half g_hlo[(size_t)B_TOTAL * 512];
__device__ __half g_w1hi[512 * 64];    // W1^T [n=512][k=64]
__device__ __half g_w1lo[512 * 64];
__device__ __half g_w2hi[512 * 512];   // (W2*eta)^T [n=512][k=512]
__device__ __half g_w2lo[512 * 512];

__device__ __forceinline__ void split_h(float v, __half& hi, __half& lo) {
    hi = __float2half_rn(v);
    lo = __float2half_rn(v - __half2float(hi));
}

// ---------------- pack kernels ----------------
__global__ void pack_x_kernel(const float* __restrict__ x) {
    size_t i = (size_t)blockIdx.x * blockDim.x + threadIdx.x;  // B*64
    __half hi, lo;
    split_h(x[i], hi, lo);
    g_xhi[i] = hi;
    g_xlo[i] = lo;
}
__global__ void pack_w1_kernel(const float* __restrict__ W1) {
    int i = blockIdx.x * blockDim.x + threadIdx.x;   // 512*64
    int n = i >> 6, k = i & 63;
    __half hi, lo;
    split_h(W1[k * 512 + n], hi, lo);
    g_w1hi[i] = hi;    // [n][k] layout, i = n*64+k
    g_w1lo[i] = lo;
}
__global__ void pack_w2_kernel(const float* __restrict__ W2,
                               const float* __restrict__ eta) {
    int i = blockIdx.x * blockDim.x + threadIdx.x;   // 512*512
    int n = i >> 9, k = i & 511;
    __half hi, lo;
    split_h(W2[k * 513 + n] * eta[0], hi, lo);
    g_w2hi[i] = hi;    // [n][k], i = n*512+k
    g_w2lo[i] = lo;
}

#define LDSM_X4(r0, r1, r2, r3, addr)                                        \
    asm volatile(                                                            \
        "ldmatrix.sync.aligned.m8n8.x4.shared.b16 {%0,%1,%2,%3}, [%4];"      \
        : "=r"(r0), "=r"(r1), "=r"(r2), "=r"(r3) : "r"(addr))

#define MMA16816(d, a, b)                                                    \
    asm volatile(                                                            \
        "mma.sync.aligned.m16n8k16.row.col.f32.f16.f16.f32 "                 \
        "{%0,%1,%2,%3}, {%4,%5,%6,%7}, {%8,%9}, {%0,%1,%2,%3};"              \
        : "+f"((d)[0]), "+f"((d)[1]), "+f"((d)[2]), "+f"((d)[3])             \
        : "r"((a)[0]), "r"((a)[1]), "r"((a)[2]), "r"((a)[3]),                \
          "r"((b)[0]), "r"((b)[1]))

// ---------------------------------------------------------------------------
// PHASE 1: h = relu(x@W1+b1), fp16x3 fused hi/lo chunks (KSEG=64, NC=2).
// CTA 256 thr, 2 CTAs/SM, tile M128xN128, smem-staged coalesced h stores.
// ---------------------------------------------------------------------------
__global__ __launch_bounds__(256, 2)
void mma_phase1_kernel(const float* __restrict__ bias) {
    constexpr int NC = 2;
    constexpr int SSTRIDE = 128;        // 64 halves * 2B
    constexpr int STAGES = 3;
    constexpr int CHUNK_BYTES = 32768;

    extern __shared__ char smem[];
    const uint32_t sbase = (uint32_t)__cvta_generic_to_shared(smem);

    const int tid = threadIdx.x;
    const int lane = tid & 31;
    const int wid = tid >> 5;
    const int wm = (wid & 3) * 32;
    const int wn = (wid >> 2) * 64;
    const int blockRow = blockIdx.y * 128;
    const int colbase = blockIdx.x * 128;

    float acc[2][8][4];
#pragma unroll
    for (int mi = 0; mi < 2; mi++)
#pragma unroll
        for (int nj = 0; nj < 8; nj++)
#pragma unroll
            for (int q = 0; q < 4; q++) acc[mi][nj][q] = 0.0f;

    const int aRow = wm + (lane & 7) + ((lane >> 3) & 1) * 8;
    const int aU = (lane >> 4) & 1;
    const int aX = aRow & 7;
    const int bRow = wn + (lane & 7) + ((lane >> 4) & 1) * 8;
    const int bU = (lane >> 3) & 1;
    const int bX = bRow & 7;

    auto loadc = [&](int kc) {
        const char* ah = (const char*)g_xhi + (size_t)blockRow * SSTRIDE + (size_t)kc * 64;
        const char* al = (const char*)g_xlo + (size_t)blockRow * SSTRIDE + (size_t)kc * 64;
        const char* bh = (const char*)g_w1hi + (size_t)colbase * SSTRIDE + (size_t)kc * 64;
        const char* bl = (const char*)g_w1lo + (size_t)colbase * SSTRIDE + (size_t)kc * 64;
        uint32_t ab = sbase + (uint32_t)(kc % STAGES) * CHUNK_BYTES;
        uint32_t bb = ab + 16384u;
#pragma unroll
        for (int j = 0; j < 4; j++) {
            int gi = tid + 256 * j;
            int row = gi >> 3, u = gi & 7;
            const char* base = (u < 4) ? ah : al;
            const char* src = base + (size_t)row * SSTRIDE + (u & 3) * 16;
            uint32_t dst = ab + row * 128u + (uint32_t)((u ^ (row & 7)) << 4);
            asm volatile("cp.async.cg.shared.global [%0], [%1], 16;"
                         :: "r"(dst), "l"(src));
        }
#pragma unroll
        for (int j = 0; j < 4; j++) {
            int gi = tid + 256 * j;
            int row = gi >> 3, u = gi & 7;
            const char* base = (u < 4) ? bh : bl;
            const char* src = base + (size_t)row * SSTRIDE + (u & 3) * 16;
            uint32_t dst = bb + row * 128u + (uint32_t)((u ^ (row & 7)) << 4);
            asm volatile("cp.async.cg.shared.global [%0], [%1], 16;"
                         :: "r"(dst), "l"(src));
        }
        asm volatile("cp.async.commit_group;");
    };

#pragma unroll
    for (int s = 0; s < STAGES - 1; s++) {
        if (s < NC) loadc(s);
        else asm volatile("cp.async.commit_group;");
    }
    asm volatile("cp.async.wait_group %0;" :: "n"(STAGES - 2));
    __syncthreads();

#pragma unroll 1
    for (int c = 0; c < NC; c++) {
        asm volatile("cp.async.commit_group;");
        uint32_t ab = sbase + (uint32_t)(c % STAGES) * CHUNK_BYTES;
        uint32_t bb = ab + 16384u;
#pragma unroll
        for (int kk = 0; kk < 2; kk++) {
            uint32_t a_hi[2][4], a_lo[2][4];
            uint32_t b_hi[8][2], b_lo[8][2];
#pragma unroll
            for (int mi = 0; mi < 2; mi++) {
                int row = aRow + mi * 16;
                uint32_t addr_h = ab + row * 128u + (uint32_t)(((kk * 2 + aU) ^ aX) << 4);
                LDSM_X4(a_hi[mi][0], a_hi[mi][1], a_hi[mi][2], a_hi[mi][3], addr_h);
            }
#pragma unroll
            for (int p = 0; p < 4; p++) {
                int row = bRow + p * 16;
                uint32_t addr_h = bb + row * 128u + (uint32_t)(((kk * 2 + bU) ^ bX) << 4);
                LDSM_X4(b_hi[2 * p][0], b_hi[2 * p][1],
                        b_hi[2 * p + 1][0], b_hi[2 * p + 1][1], addr_h);
            }
#pragma unroll
            for (int mi = 0; mi < 2; mi++) {
                int row = aRow + mi * 16;
                uint32_t addr_l = ab + row * 128u + (uint32_t)(((4 + kk * 2 + aU) ^ aX) << 4);
                LDSM_X4(a_lo[mi][0], a_lo[mi][1], a_lo[mi][2], a_lo[mi][3], addr_l);
            }
#pragma unroll
            for (int mi = 0; mi < 2; mi++)
#pragma unroll
                for (int nj = 0; nj < 8; nj++)
                    MMA16816(acc[mi][nj], a_hi[mi], b_hi[nj]);
#pragma unroll
            for (int p = 0; p < 4; p++) {
                int row = bRow + p * 16;
                uint32_t addr_l = bb + row * 128u + (uint32_t)(((4 + kk * 2 + bU) ^ bX) << 4);
                LDSM_X4(b_lo[2 * p][0], b_lo[2 * p][1],
                        b_lo[2 * p + 1][0], b_lo[2 * p + 1][1], addr_l);
            }
#pragma unroll
            for (int mi = 0; mi < 2; mi++)
#pragma unroll
                for (int nj = 0; nj < 8; nj++)
                    MMA16816(acc[mi][nj], a_lo[mi], b_hi[nj]);
#pragma unroll
            for (int mi = 0; mi < 2; mi++)
#pragma unroll
                for (int nj = 0; nj < 8; nj++)
                    MMA16816(acc[mi][nj], a_hi[mi], b_lo[nj]);
        }
        asm volatile("cp.async.wait_group %0;" :: "n"(STAGES - 2));
        __syncthreads();
    }

    // epilogue: relu + split, staged in smem, coalesced stores
    const int g = lane >> 2;
    const int tig = lane & 3;
    __half* s_hi = reinterpret_cast<__half*>(smem);             // 128x136
    __half* s_lo = reinterpret_cast<__half*>(smem + 128 * 272); // 128x136
#pragma unroll
    for (int mi = 0; mi < 2; mi++)
#pragma unroll
        for (int rsel = 0; rsel < 2; rsel++) {
            int rloc = wm + mi * 16 + g + rsel * 8;
#pragma unroll
            for (int nj = 0; nj < 8; nj++) {
                int cloc = wn + nj * 8 + 2 * tig;
                int cc = colbase + cloc;
                float h0 = fmaxf(acc[mi][nj][rsel * 2 + 0] + bias[cc], 0.0f);
                float h1 = fmaxf(acc[mi][nj][rsel * 2 + 1] + bias[cc + 1], 0.0f);
                __half hi0, lo0, hi1, lo1;
                split_h(h0, hi0, lo0);
                split_h(h1, hi1, lo1);
                *reinterpret_cast<__half2*>(&s_hi[rloc * 136 + cloc]) =
                    __halves2half2(hi0, hi1);
                *reinterpret_cast<__half2*>(&s_lo[rloc * 136 + cloc]) =
                    __halves2half2(lo0, lo1);
            }
        }
    __syncthreads();
#pragma unroll
    for (int it = 0; it < 8; it++) {
        int idx = tid + it * 256;
        int row = idx >> 4, seg = idx & 15;
        uint4 v = *reinterpret_cast<uint4*>(&s_hi[row * 136 + seg * 8]);
        *reinterpret_cast<uint4*>(
            &g_hhi[(size_t)(blockRow + row) * 512 + colbase + seg * 8]) = v;
        uint4 w = *reinterpret_cast<uint4*>(&s_lo[row * 136 + seg * 8]);
        *reinterpret_cast<uint4*>(
            &g_hlo[(size_t)(blockRow + row) * 512 + colbase + seg * 8]) = w;
    }
}

// ---------------------------------------------------------------------------
// PHASE 2 (PERSISTENT): params = h@(W2*eta), Moebius epilogue.
// 296 CTAs (2/SM, one wave). Slot s handles jobs jidx = s + 296*i.
// jidx -> colbase=(jidx&3)*128, blockRow=(jidx>>2)*128 (4 row-sharing CTAs
// concurrent -> A L2-hot). cp.async pipeline flattened ACROSS jobs: no
// per-wave refill; each job's epilogue overlaps the next job's loads.
// smem: 3x32KB chunk stages + 8.5KB epilogue staging (104.5KB/CTA).
// ---------------------------------------------------------------------------
__global__ __launch_bounds__(256, 2)
void mma_phase2_persistent(const float* __restrict__ bias,
                           const float* __restrict__ theta,
                           const float* __restrict__ r_in,
                           const float* __restrict__ eta,
                           float* __restrict__ out) {
    constexpr int SSTRIDE = 1024;       // 512 halves * 2B
    constexpr int STAGES = 3;
    constexpr int CHUNK_BYTES = 32768;

    extern __shared__ char smem[];
    const uint32_t sbase = (uint32_t)__cvta_generic_to_shared(smem);
    float* s_out = reinterpret_cast<float*>(smem + 3 * CHUNK_BYTES); // 128x17

    const int tid = threadIdx.x;
    const int lane = tid & 31;
    const int wid = tid >> 5;
    const int wm = (wid & 3) * 32;
    const int wn = (wid >> 2) * 64;
    const int slot = blockIdx.x;
    const int njobs = (NJOBS_TOT - slot + NSLOTS - 1) / NSLOTS;
    const int totalChunks = njobs * 16;
    const float e = eta[0];

    float acc[2][8][4];
#pragma unroll
    for (int mi = 0; mi < 2; mi++)
#pragma unroll
        for (int nj = 0; nj < 8; nj++)
#pragma unroll
            for (int q = 0; q < 4; q++) acc[mi][nj][q] = 0.0f;

    const int aRow = wm + (lane & 7) + ((lane >> 3) & 1) * 8;
    const int aU = (lane >> 4) & 1;
    const int aX = aRow & 7;
    const int bRow = wn + (lane & 7) + ((lane >> 4) & 1) * 8;
    const int bU = (lane >> 3) & 1;
    const int bX = bRow & 7;
    const int g = lane >> 2;
    const int tig = lane & 3;

    // load chunk gc (global index): job = gc/16, kc = gc%16
    auto loadc = [&](int gc) {
        int j = gc >> 4, kc = gc & 15;
        int jidx = slot + NSLOTS * j;
        int blockRow = (jidx >> 2) * 128;
        int colbase = (jidx & 3) * 128;
        const char* ah = (const char*)g_hhi + (size_t)blockRow * SSTRIDE + (size_t)kc * 64;
        const char* al = (const char*)g_hlo + (size_t)blockRow * SSTRIDE + (size_t)kc * 64;
        const char* bh = (const char*)g_w2hi + (size_t)colbase * SSTRIDE + (size_t)kc * 64;
        const char* bl = (const char*)g_w2lo + (size_t)colbase * SSTRIDE + (size_t)kc * 64;
        uint32_t ab = sbase + (uint32_t)(gc % STAGES) * CHUNK_BYTES;
        uint32_t bb = ab + 16384u;
#pragma unroll
        for (int jj = 0; jj < 4; jj++) {
            int gi = tid + 256 * jj;
            int row = gi >> 3, u = gi & 7;
            const char* base = (u < 4) ? ah : al;
            const char* src = base + (size_t)row * SSTRIDE + (u & 3) * 16;
            uint32_t dst = ab + row * 128u + (uint32_t)((u ^ (row & 7)) << 4);
            asm volatile("cp.async.cg.shared.global [%0], [%1], 16;"
                         :: "r"(dst), "l"(src));
        }
#pragma unroll
        for (int jj = 0; jj < 4; jj++) {
            int gi = tid + 256 * jj;
            int row = gi >> 3, u = gi & 7;
            const char* base = (u < 4) ? bh : bl;
            const char* src = base + (size_t)row * SSTRIDE + (u & 3) * 16;
            uint32_t dst = bb + row * 128u + (uint32_t)((u ^ (row & 7)) << 4);
            asm volatile("cp.async.cg.shared.global [%0], [%1], 16;"
                         :: "r"(dst), "l"(src));
        }
        asm volatile("cp.async.commit_group;");
    };

    // prologue: chunks 0,1 in flight
    loadc(0);
    loadc(1);
    asm volatile("cp.async.wait_group 1;");
    __syncthreads();   // chunk 0 visible

#pragma unroll 1
    for (int gc = 0; gc < totalChunks; gc++) {
        if (gc + 2 < totalChunks) loadc(gc + 2);
        else asm volatile("cp.async.commit_group;");

        uint32_t ab = sbase + (uint32_t)(gc % STAGES) * CHUNK_BYTES;
        uint32_t bb = ab + 16384u;
#pragma unroll
        for (int kk = 0; kk < 2; kk++) {
            uint32_t a_hi[2][4], a_lo[2][4];
            uint32_t b_hi[8][2], b_lo[8][2];
#pragma unroll
            for (int mi = 0; mi < 2; mi++) {
                int row = aRow + mi * 16;
                uint32_t addr_h = ab + row * 128u + (uint32_t)(((kk * 2 + aU) ^ aX) << 4);
                LDSM_X4(a_hi[mi][0], a_hi[mi][1], a_hi[mi][2], a_hi[mi][3], addr_h);
            }
#pragma unroll
            for (int p = 0; p < 4; p++) {
                int row = bRow + p * 16;
                uint32_t addr_h = bb + row * 128u + (uint32_t)(((kk * 2 + bU) ^ bX) << 4);
                LDSM_X4(b_hi[2 * p][0], b_hi[2 * p][1],
                        b_hi[2 * p + 1][0], b_hi[2 * p + 1][1], addr_h);
            }
#pragma unroll
            for (int mi = 0; mi < 2; mi++) {
                int row = aRow + mi * 16;
                uint32_t addr_l = ab + row * 128u + (uint32_t)(((4 + kk * 2 + aU) ^ aX) << 4);
                LDSM_X4(a_lo[mi][0], a_lo[mi][1], a_lo[mi][2], a_lo[mi][3], addr_l);
            }
#pragma unroll
            for (int mi = 0; mi < 2; mi++)
#pragma unroll
                for (int nj = 0; nj < 8; nj++)
                    MMA16816(acc[mi][nj], a_hi[mi], b_hi[nj]);
#pragma unroll
            for (int p = 0; p < 4; p++) {
                int row = bRow + p * 16;
                uint32_t addr_l = bb + row * 128u + (uint32_t)(((4 + kk * 2 + bU) ^ bX) << 4);
                LDSM_X4(b_lo[2 * p][0], b_lo[2 * p][1],
                        b_lo[2 * p + 1][0], b_lo[2 * p + 1][1], addr_l);
            }
#pragma unroll
            for (int mi = 0; mi < 2; mi++)
#pragma unroll
                for (int nj = 0; nj < 8; nj++)
                    MMA16816(acc[mi][nj], a_lo[mi], b_hi[nj]);
#pragma unroll
            for (int mi = 0; mi < 2; mi++)
#pragma unroll
                for (int nj = 0; nj < 8; nj++)
                    MMA16816(acc[mi][nj], a_hi[mi], b_lo[nj]);
        }
        asm volatile("cp.async.wait_group %0;" :: "n"(STAGES - 2));
        __syncthreads();

        if ((gc & 15) == 15) {
            // ---- job epilogue (overlaps next job's in-flight loads) ----
            int jidx = slot + NSLOTS * (gc >> 4);
            int blockRow = (jidx >> 2) * 128;
            int colbase = (jidx & 3) * 128;
            const int dbase = (colbase + wn) >> 4;
            const int d0c = colbase >> 4;

            float bb2[8][2];
#pragma unroll
            for (int nj = 0; nj < 8; nj++) {
                int cc = colbase + wn + nj * 8 + 2 * tig;
                bb2[nj][0] = bias[cc] * e;
                bb2[nj][1] = bias[cc + 1] * e;
            }
#pragma unroll
            for (int mi = 0; mi < 2; mi++)
#pragma unroll
                for (int rsel = 0; rsel < 2; rsel++) {
                    int rloc = wm + mi * 16 + g + rsel * 8;
                    int grow = blockRow + rloc;
#pragma unroll
                    for (int dj = 0; dj < 4; dj++) {
                        int d = dbase + dj;
                        float th = theta[grow * DH + d];
                        float rr = r_in[grow * DH + d];
                        float sn, cs;
                        sincosf(th, &sn, &cs);
                        float z0 = rr * cs, z1 = rr * sn;
                        float rr2 = rr * rr;
                        float sumT = 0.0f, sumS = 0.0f;
#pragma unroll
                        for (int hf = 0; hf < 2; hf++) {
                            int nj = 2 * dj + hf;
                            float p0 = acc[mi][nj][rsel * 2 + 0] + bb2[nj][0];
                            float p1 = acc[mi][nj][rsel * 2 + 1] + bb2[nj][1];
                            float nrm = sqrtf(p0 * p0 + p1 * p1);
                            float f = rr * 0.99f / (1.0f + nrm);
                            float w0 = f * p0, w1 = f * p1;
                            float zw0 = z0 - w0, zw1 = z1 - w1;
                            float dist2 = zw0 * zw0 + zw1 * zw1;
                            float scale = (rr2 - (w0 * w0 + w1 * w1)) / dist2;
                            float zo0 = scale * zw0 - w0;
                            float zo1 = scale * zw1 - w1;
                            float ang = atan2f(zo1, zo0);
                            if (ang < 0.0f) ang += TWO_PI_F;
                            sumT += ang;
                            sumS += scale;
                        }
                        sumT += __shfl_xor_sync(0xffffffffu, sumT, 1);
                        sumS += __shfl_xor_sync(0xffffffffu, sumS, 1);
                        sumT += __shfl_xor_sync(0xffffffffu, sumT, 2);
                        sumS += __shfl_xor_sync(0xffffffffu, sumS, 2);
                        if (tig == 0) {
                            int dl = d - d0c;
                            s_out[rloc * 17 + dl] = sumT * 0.125f;
                            s_out[rloc * 17 + 8 + dl] = logf(sumS * 0.125f + 1e-8f);
                        }
                    }
                }
            __syncthreads();
#pragma unroll
            for (int it = 0; it < 8; it++) {
                int idx = tid + it * 256;
                int row = idx >> 4;
                int rest = idx & 15;
                int t = rest >> 3;
                int dl = rest & 7;
                float v = s_out[row * 17 + t * 8 + dl];
                out[(size_t)t * B_TOTAL * DH + (size_t)(blockRow + row) * DH +
                    d0c + dl] = v;
            }
            // re-zero accumulators for the next job
#pragma unroll
            for (int mi = 0; mi < 2; mi++)
#pragma unroll
                for (int nj = 0; nj < 8; nj++)
#pragma unroll
                    for (int q = 0; q < 4; q++) acc[mi][nj][q] = 0.0f;
        }
    }
}

// ---------------- launch ----------------
extern "C" void kernel_launch(void* const* d_in, const int* in_sizes, int n_in,
                              void* d_out, int out_size) {
    const float* theta = (const float*)d_in[0];
    const float* r     = (const float*)d_in[1];
    const float* x     = (const float*)d_in[2];
    const float* W1    = (const float*)d_in[3];
    const float* b1    = (const float*)d_in[4];
    const float* W2    = (const float*)d_in[5];
    const float* b2    = (const float*)d_in[6];
    const float* eta   = (const float*)d_in[7];
    float* out = (float*)d_out;

    pack_x_kernel<<<(B_TOTAL * 64) / 256, 256>>>(x);
    pack_w1_kernel<<<(512 * 64) / 256, 256>>>(W1);
    pack_w2_kernel<<<(512 * 512) / 256, 256>>>(W2, eta);

    const int smem1 = 3 * 32768;                    // 96 KB
    const int smem2 = 3 * 32768 + 128 * 17 * 4;    // 96 KB + 8.5 KB staging
    cudaFuncSetAttribute(mma_phase1_kernel,
                         cudaFuncAttributeMaxDynamicSharedMemorySize, smem1);
    cudaFuncSetAttribute(mma_phase2_persistent,
                         cudaFuncAttributeMaxDynamicSharedMemorySize, smem2);

    dim3 grid1(4, B_TOTAL / 128);
    mma_phase1_kernel<<<grid1, 256, smem1>>>(b1);
    mma_phase2_persistent<<<NSLOTS, 256, smem2>>>(b2, theta, r, eta, out);
}

// round 13
// speedup vs baseline: 1.0336x; 1.0336x over previous
#include <cuda_runtime.h>
#include <cuda_fp16.h>
#include <math.h>
#include <stdint.h>

// ---------------- problem constants ----------------
#define B_TOTAL   131072
#define DH        32
#define TWO_PI_F  6.283185307179586f
#define NJOBS1    4096   // phase-1 jobs (1024 rows x 4 col quarters)

// ---------------- device scratch (static, no alloc) ----------------
__device__ __half g_xhi[(size_t)B_TOTAL * 64];
__device__ __half g_xlo[(size_t)B_TOTAL * 64];
__device__ __half g_hhi[(size_t)B_TOTAL * 512];
__device__ __half g_hlo[(size_t)B_TOTAL * 512];
__device__ __half g_w1hi[512 * 64];    // W1^T [n=512][k=64]
__device__ __half g_w1lo[512 * 64];
__device__ __half g_w2hi[512 * 512];   // (W2*eta)^T [n=512][k=512]
__device__ __half g_w2lo[512 * 512];
__device__ int    g_ready[1024];       // per-row-tile phase-1 completion count

__device__ __forceinline__ void split_h(float v, __half& hi, __half& lo) {
    hi = __float2half_rn(v);
    lo = __float2half_rn(v - __half2float(hi));
}

// ---------------- combined pack + flag-reset kernel ----------------
__global__ void pack_all_kernel(const float* __restrict__ x,
                                const float* __restrict__ W1,
                                const float* __restrict__ W2,
                                const float* __restrict__ eta) {
    int bid = blockIdx.x, tid = threadIdx.x;
    if (bid < 4) g_ready[bid * 256 + tid] = 0;
    if (bid < 32768) {                       // x: B*64 / 256
        size_t i = (size_t)bid * 256 + tid;
        __half hi, lo;
        split_h(x[i], hi, lo);
        g_xhi[i] = hi;
        g_xlo[i] = lo;
    } else if (bid < 32768 + 128) {          // W1^T: 512*64 / 256
        int i = (bid - 32768) * 256 + tid;
        int n = i >> 6, k = i & 63;
        __half hi, lo;
        split_h(W1[k * 512 + n], hi, lo);
        g_w1hi[i] = hi;
        g_w1lo[i] = lo;
    } else {                                 // W2^T*eta: 512*512 / 256
        int i = (bid - 32896) * 256 + tid;
        int n = i >> 9, k = i & 511;
        __half hi, lo;
        split_h(W2[k * 513 + n] * eta[0], hi, lo);
        g_w2hi[i] = hi;
        g_w2lo[i] = lo;
    }
}

#define LDSM_X4(r0, r1, r2, r3, addr)                                        \
    asm volatile(                                                            \
        "ldmatrix.sync.aligned.m8n8.x4.shared.b16 {%0,%1,%2,%3}, [%4];"      \
        : "=r"(r0), "=r"(r1), "=r"(r2), "=r"(r3) : "r"(addr))

#define MMA16816(d, a, b)                                                    \
    asm volatile(                                                            \
        "mma.sync.aligned.m16n8k16.row.col.f32.f16.f16.f32 "                 \
        "{%0,%1,%2,%3}, {%4,%5,%6,%7}, {%8,%9}, {%0,%1,%2,%3};"              \
        : "+f"((d)[0]), "+f"((d)[1]), "+f"((d)[2]), "+f"((d)[3])             \
        : "r"((a)[0]), "r"((a)[1]), "r"((a)[2]), "r"((a)[3]),                \
          "r"((b)[0]), "r"((b)[1]))

// one fused hi/lo k32 chunk load: A rows [blockRow,+128), B rows [colbase,+128)
// smem row = [hi 64B | lo 64B], 16B-XOR swizzle. SSTR = source row stride (B).
#define LOADC(AH, AL, BH, BL, SSTR, blockRow, colbase, kc, buf)              \
    do {                                                                     \
        const char* ah_ = (const char*)(AH) + (size_t)(blockRow) * (SSTR) +  \
                          (size_t)(kc) * 64;                                 \
        const char* al_ = (const char*)(AL) + (size_t)(blockRow) * (SSTR) +  \
                          (size_t)(kc) * 64;                                 \
        const char* bh_ = (const char*)(BH) + (size_t)(colbase) * (SSTR) +   \
                          (size_t)(kc) * 64;                                 \
        const char* bl_ = (const char*)(BL) + (size_t)(colbase) * (SSTR) +   \
                          (size_t)(kc) * 64;                                 \
        uint32_t ab_ = sbase + (uint32_t)(buf) * 32768u;                     \
        uint32_t bb_ = ab_ + 16384u;                                         \
        _Pragma("unroll")                                                    \
        for (int j_ = 0; j_ < 4; j_++) {                                     \
            int gi_ = tid + 256 * j_;                                        \
            int row_ = gi_ >> 3, u_ = gi_ & 7;                               \
            const char* src_ = ((u_ < 4) ? ah_ : al_) +                      \
                               (size_t)row_ * (SSTR) + (u_ & 3) * 16;        \
            uint32_t dst_ = ab_ + row_ * 128u +                              \
                            (uint32_t)((u_ ^ (row_ & 7)) << 4);              \
            asm volatile("cp.async.cg.shared.global [%0], [%1], 16;"         \
                         :: "r"(dst_), "l"(src_));                           \
        }                                                                    \
        _Pragma("unroll")                                                    \
        for (int j_ = 0; j_ < 4; j_++) {                                     \
            int gi_ = tid + 256 * j_;                                        \
            int row_ = gi_ >> 3, u_ = gi_ & 7;                               \
            const char* src_ = ((u_ < 4) ? bh_ : bl_) +                      \
                               (size_t)row_ * (SSTR) + (u_ & 3) * 16;        \
            uint32_t dst_ = bb_ + row_ * 128u +                              \
                            (uint32_t)((u_ ^ (row_ & 7)) << 4);              \
            asm volatile("cp.async.cg.shared.global [%0], [%1], 16;"         \
                         :: "r"(dst_), "l"(src_));                           \
        }                                                                    \
        asm volatile("cp.async.commit_group;");                              \
    } while (0)

// one k32 fused-chunk compute: 3 products x 2 k16 steps into acc[2][8][4]
#define CHUNK_MMA(buf)                                                       \
    do {                                                                     \
        uint32_t ab_ = sbase + (uint32_t)(buf) * 32768u;                     \
        uint32_t bb_ = ab_ + 16384u;                                         \
        _Pragma("unroll")                                                    \
        for (int kk = 0; kk < 2; kk++) {                                     \
            uint32_t a_hi[2][4], a_lo[2][4];                                 \
            uint32_t b_hi[8][2], b_lo[8][2];                                 \
            _Pragma("unroll")                                                \
            for (int mi = 0; mi < 2; mi++) {                                 \
                int row = aRow + mi * 16;                                    \
                uint32_t ah_ = ab_ + row * 128u +                            \
                               (uint32_t)(((kk * 2 + aU) ^ aX) << 4);        \
                LDSM_X4(a_hi[mi][0], a_hi[mi][1], a_hi[mi][2], a_hi[mi][3],  \
                        ah_);                                                \
            }                                                                \
            _Pragma("unroll")                                                \
            for (int p = 0; p < 4; p++) {                                    \
                int row = bRow + p * 16;                                     \
                uint32_t bh_ = bb_ + row * 128u +                            \
                               (uint32_t)(((kk * 2 + bU) ^ bX) << 4);        \
                LDSM_X4(b_hi[2 * p][0], b_hi[2 * p][1],                      \
                        b_hi[2 * p + 1][0], b_hi[2 * p + 1][1], bh_);        \
            }                                                                \
            _Pragma("unroll")                                                \
            for (int mi = 0; mi < 2; mi++) {                                 \
                int row = aRow + mi * 16;                                    \
                uint32_t al_ = ab_ + row * 128u +                            \
                               (uint32_t)(((4 + kk * 2 + aU) ^ aX) << 4);    \
                LDSM_X4(a_lo[mi][0], a_lo[mi][1], a_lo[mi][2], a_lo[mi][3],  \
                        al_);                                                \
            }                                                                \
            _Pragma("unroll")                                                \
            for (int mi = 0; mi < 2; mi++)                                   \
                _Pragma("unroll")                                            \
                for (int nj = 0; nj < 8; nj++)                               \
                    MMA16816(acc[mi][nj], a_hi[mi], b_hi[nj]);               \
            _Pragma("unroll")                                                \
            for (int p = 0; p < 4; p++) {                                    \
                int row = bRow + p * 16;                                     \
                uint32_t bl_ = bb_ + row * 128u +                            \
                               (uint32_t)(((4 + kk * 2 + bU) ^ bX) << 4);    \
                LDSM_X4(b_lo[2 * p][0], b_lo[2 * p][1],                      \
                        b_lo[2 * p + 1][0], b_lo[2 * p + 1][1], bl_);        \
            }                                                                \
            _Pragma("unroll")                                                \
            for (int mi = 0; mi < 2; mi++)                                   \
                _Pragma("unroll")                                            \
                for (int nj = 0; nj < 8; nj++)                               \
                    MMA16816(acc[mi][nj], a_lo[mi], b_hi[nj]);               \
            _Pragma("unroll")                                                \
            for (int mi = 0; mi < 2; mi++)                                   \
                _Pragma("unroll")                                            \
                for (int nj = 0; nj < 8; nj++)                               \
                    MMA16816(acc[mi][nj], a_hi[mi], b_lo[nj]);               \
        }                                                                    \
    } while (0)

// ---------------------------------------------------------------------------
// Fused kernel: bids [0,4096) = phase-1 jobs, [4096,8192) = phase-2 jobs.
// Phase-1 publishes per-row completion flags; phase-2 spin-waits on them
// (bid-ordered dispatch => all producers dispatched before any consumer).
// Both phases: 256 thr, 2 CTAs/SM, M128xN128, warp 32x64, 3-stage 32KB chunks.
// Phase-2 prefetches theta/r/bias to smem in a leading cp.async group.
// ---------------------------------------------------------------------------
__global__ __launch_bounds__(256, 2)
void fused_moebius_kernel(const float* __restrict__ b1,
                          const float* __restrict__ b2,
                          const float* __restrict__ theta,
                          const float* __restrict__ r_in,
                          const float* __restrict__ eta,
                          float* __restrict__ out) {
    extern __shared__ char smem[];
    const uint32_t sbase = (uint32_t)__cvta_generic_to_shared(smem);

    const int tid = threadIdx.x;
    const int lane = tid & 31;
    const int wid = tid >> 5;
    const int wm = (wid & 3) * 32;
    const int wn = (wid >> 2) * 64;

    const int aRow = wm + (lane & 7) + ((lane >> 3) & 1) * 8;
    const int aU = (lane >> 4) & 1;
    const int aX = aRow & 7;
    const int bRow = wn + (lane & 7) + ((lane >> 4) & 1) * 8;
    const int bU = (lane >> 3) & 1;
    const int bX = bRow & 7;
    const int g = lane >> 2;
    const int tig = lane & 3;

    float acc[2][8][4];
#pragma unroll
    for (int mi = 0; mi < 2; mi++)
#pragma unroll
        for (int nj = 0; nj < 8; nj++)
#pragma unroll
            for (int q = 0; q < 4; q++) acc[mi][nj][q] = 0.0f;

    if (blockIdx.x < NJOBS1) {
        // ================= PHASE 1: h = relu(x@W1+b1), split =================
        const int jid = blockIdx.x;
        const int blockRow = (jid >> 2) * 128;
        const int colbase = (jid & 3) * 128;
        constexpr int SSTR = 128;   // 64 halves * 2B

        LOADC(g_xhi, g_xlo, g_w1hi, g_w1lo, SSTR, blockRow, colbase, 0, 0);
        LOADC(g_xhi, g_xlo, g_w1hi, g_w1lo, SSTR, blockRow, colbase, 1, 1);
        asm volatile("cp.async.wait_group 1;");
        __syncthreads();
        CHUNK_MMA(0);
        asm volatile("cp.async.wait_group 0;");
        __syncthreads();
        CHUNK_MMA(1);

        // epilogue: relu + split, staged in smem, coalesced stores
        __half* s_hi = reinterpret_cast<__half*>(smem);             // 128x136
        __half* s_lo = reinterpret_cast<__half*>(smem + 128 * 272); // 128x136
        __syncthreads();   // chunk buffers free for reuse
#pragma unroll
        for (int mi = 0; mi < 2; mi++)
#pragma unroll
            for (int rsel = 0; rsel < 2; rsel++) {
                int rloc = wm + mi * 16 + g + rsel * 8;
#pragma unroll
                for (int nj = 0; nj < 8; nj++) {
                    int cloc = wn + nj * 8 + 2 * tig;
                    int cc = colbase + cloc;
                    float h0 = fmaxf(acc[mi][nj][rsel * 2 + 0] + b1[cc], 0.0f);
                    float h1 = fmaxf(acc[mi][nj][rsel * 2 + 1] + b1[cc + 1], 0.0f);
                    __half hi0, lo0, hi1, lo1;
                    split_h(h0, hi0, lo0);
                    split_h(h1, hi1, lo1);
                    *reinterpret_cast<__half2*>(&s_hi[rloc * 136 + cloc]) =
                        __halves2half2(hi0, hi1);
                    *reinterpret_cast<__half2*>(&s_lo[rloc * 136 + cloc]) =
                        __halves2half2(lo0, lo1);
                }
            }
        __syncthreads();
#pragma unroll
        for (int it = 0; it < 8; it++) {
            int idx = tid + it * 256;
            int row = idx >> 4, seg = idx & 15;
            uint4 v = *reinterpret_cast<uint4*>(&s_hi[row * 136 + seg * 8]);
            *reinterpret_cast<uint4*>(
                &g_hhi[(size_t)(blockRow + row) * 512 + colbase + seg * 8]) = v;
            uint4 w = *reinterpret_cast<uint4*>(&s_lo[row * 136 + seg * 8]);
            *reinterpret_cast<uint4*>(
                &g_hlo[(size_t)(blockRow + row) * 512 + colbase + seg * 8]) = w;
        }
        // publish completion (release)
        __threadfence();
        __syncthreads();
        if (tid == 0) atomicAdd(&g_ready[jid >> 2], 1);
    } else {
        // ============ PHASE 2: params = h@(W2*eta), Moebius map =============
        const int jid = blockIdx.x - NJOBS1;
        const int blockRow = (jid >> 2) * 128;
        const int colbase = (jid & 3) * 128;
        constexpr int SSTR = 1024;  // 512 halves * 2B
        constexpr int NC = 16;

        float* s_th = reinterpret_cast<float*>(smem + 98304);          // 128x12
        float* s_rr = reinterpret_cast<float*>(smem + 98304 + 6144);   // 128x12
        float* s_b2 = reinterpret_cast<float*>(smem + 98304 + 12288);  // 128

        // G0: prefetch theta/r (32B per row) + bias slice, before the spin
        {
            int row = tid >> 1, seg = tid & 1;
            const char* st = (const char*)theta +
                             (size_t)(blockRow + row) * 128 + (jid & 3) * 32 +
                             seg * 16;
            uint32_t dt = sbase + 98304u + row * 48u + seg * 16u;
            asm volatile("cp.async.ca.shared.global [%0], [%1], 16;"
                         :: "r"(dt), "l"(st));
            const char* sr = (const char*)r_in +
                             (size_t)(blockRow + row) * 128 + (jid & 3) * 32 +
                             seg * 16;
            uint32_t dr = sbase + 98304u + 6144u + row * 48u + seg * 16u;
            asm volatile("cp.async.ca.shared.global [%0], [%1], 16;"
                         :: "r"(dr), "l"(sr));
            if (tid < 32) {
                const char* sb = (const char*)b2 + colbase * 4 + tid * 16;
                uint32_t db = sbase + 98304u + 12288u + tid * 16u;
                asm volatile("cp.async.ca.shared.global [%0], [%1], 16;"
                             :: "r"(db), "l"(sb));
            }
            asm volatile("cp.async.commit_group;");
        }

        // acquire: wait until all 4 producers of this row tile finished
        if (tid == 0) {
            while (atomicAdd(&g_ready[jid >> 2], 0) < 4) {}
            __threadfence();
        }
        __syncthreads();

        LOADC(g_hhi, g_hlo, g_w2hi, g_w2lo, SSTR, blockRow, colbase, 0, 0);
        LOADC(g_hhi, g_hlo, g_w2hi, g_w2lo, SSTR, blockRow, colbase, 1, 1);
        asm volatile("cp.async.wait_group 1;");   // G0 + chunk0 done
        __syncthreads();

#pragma unroll 1
        for (int c = 0; c < NC; c++) {
            if (c + 2 < NC) {
                int kc = c + 2;
                LOADC(g_hhi, g_hlo, g_w2hi, g_w2lo, SSTR, blockRow, colbase,
                      kc, kc % 3);
            } else {
                asm volatile("cp.async.commit_group;");
            }
            CHUNK_MMA(c % 3);
            asm volatile("cp.async.wait_group 1;");
            __syncthreads();
        }

        // ---- Moebius epilogue (theta/r/bias from smem) ----
        const float e = eta[0];
        float bb2[8][2];
#pragma unroll
        for (int nj = 0; nj < 8; nj++) {
            int cl = wn + nj * 8 + 2 * tig;
            bb2[nj][0] = s_b2[cl] * e;
            bb2[nj][1] = s_b2[cl + 1] * e;
        }
        const int d0c = colbase >> 4;
        const int dbloc = wn >> 4;          // 0 or 4
        float* s_out = reinterpret_cast<float*>(smem);   // 128x17, overlays chunks

#pragma unroll
        for (int mi = 0; mi < 2; mi++)
#pragma unroll
            for (int rsel = 0; rsel < 2; rsel++) {
                int rloc = wm + mi * 16 + g + rsel * 8;
                int grow = blockRow + rloc;
#pragma unroll
                for (int dj = 0; dj < 4; dj++) {
                    int dl = dbloc + dj;
                    float th = s_th[rloc * 12 + dl];
                    float rr = s_rr[rloc * 12 + dl];
                    float sn, cs;
                    sincosf(th, &sn, &cs);
                    float z0 = rr * cs, z1 = rr * sn;
                    float rr2 = rr * rr;
                    float sumT = 0.0f, sumS = 0.0f;
#pragma unroll
                    for (int hf = 0; hf < 2; hf++) {
                        int nj = 2 * dj + hf;
                        float p0 = acc[mi][nj][rsel * 2 + 0] + bb2[nj][0];
                        float p1 = acc[mi][nj][rsel * 2 + 1] + bb2[nj][1];
                        float nrm = sqrtf(p0 * p0 + p1 * p1);
                        float f = rr * 0.99f / (1.0f + nrm);
                        float w0 = f * p0, w1 = f * p1;
                        float zw0 = z0 - w0, zw1 = z1 - w1;
                        float dist2 = zw0 * zw0 + zw1 * zw1;
                        float scale = (rr2 - (w0 * w0 + w1 * w1)) / dist2;
                        float zo0 = scale * zw0 - w0;
                        float zo1 = scale * zw1 - w1;
                        float ang = atan2f(zo1, zo0);
                        if (ang < 0.0f) ang += TWO_PI_F;
                        sumT += ang;
                        sumS += scale;
                    }
                    sumT += __shfl_xor_sync(0xffffffffu, sumT, 1);
                    sumS += __shfl_xor_sync(0xffffffffu, sumS, 1);
                    sumT += __shfl_xor_sync(0xffffffffu, sumT, 2);
                    sumS += __shfl_xor_sync(0xffffffffu, sumS, 2);
                    if (tig == 0) {
                        s_out[rloc * 17 + dl] = sumT * 0.125f;
                        s_out[rloc * 17 + 8 + dl] = logf(sumS * 0.125f + 1e-8f);
                    }
                }
            }
        __syncthreads();
#pragma unroll
        for (int it = 0; it < 8; it++) {
            int idx = tid + it * 256;
            int row = idx >> 4;
            int rest = idx & 15;
            int t = rest >> 3;
            int dl = rest & 7;
            float v = s_out[row * 17 + t * 8 + dl];
            out[(size_t)t * B_TOTAL * DH + (size_t)(blockRow + row) * DH +
                d0c + dl] = v;
        }
    }
}

// ---------------- launch ----------------
extern "C" void kernel_launch(void* const* d_in, const int* in_sizes, int n_in,
                              void* d_out, int out_size) {
    const float* theta = (const float*)d_in[0];
    const float* r     = (const float*)d_in[1];
    const float* x     = (const float*)d_in[2];
    const float* W1    = (const float*)d_in[3];
    const float* b1    = (const float*)d_in[4];
    const float* W2    = (const float*)d_in[5];
    const float* b2    = (const float*)d_in[6];
    const float* eta   = (const float*)d_in[7];
    float* out = (float*)d_out;

    pack_all_kernel<<<32768 + 128 + 1024, 256>>>(x, W1, W2, eta);

    const int smem_bytes = 98304 + 6144 + 6144 + 512;   // 111104 B
    cudaFuncSetAttribute(fused_moebius_kernel,
                         cudaFuncAttributeMaxDynamicSharedMemorySize, smem_bytes);
    fused_moebius_kernel<<<2 * NJOBS1, 256, smem_bytes>>>(
        b1, b2, theta, r, eta, out);
}

// round 14
// speedup vs baseline: 1.0745x; 1.0395x over previous
#include <cuda_runtime.h>
#include <cuda_fp16.h>
#include <math.h>
#include <stdint.h>

// ---------------- problem constants ----------------
#define B_TOTAL   131072
#define DH        32
#define TWO_PI_F  6.283185307179586f

// ---------------- device scratch (static, no alloc) ----------------
__device__ __half g_xhi[(size_t)B_TOTAL * 64];
__device__ __half g_xlo[(size_t)B_TOTAL * 64];
__device__ __half g_hhi[(size_t)B_TOTAL * 512];
__device__ __half g_hlo[(size_t)B_TOTAL * 512];
__device__ __half g_w1hi[512 * 64];    // W1^T [n=512][k=64]
__device__ __half g_w1lo[512 * 64];
__device__ __half g_w2hi[512 * 512];   // (W2*eta)^T [n=512][k=512]
__device__ __half g_w2lo[512 * 512];

__device__ __forceinline__ void split_h(float v, __half& hi, __half& lo) {
    hi = __float2half_rn(v);
    lo = __float2half_rn(v - __half2float(hi));
}

// ---------------- combined pack kernel ----------------
__global__ void pack_all_kernel(const float* __restrict__ x,
                                const float* __restrict__ W1,
                                const float* __restrict__ W2,
                                const float* __restrict__ eta) {
    int bid = blockIdx.x, tid = threadIdx.x;
    if (bid < 32768) {                       // x: B*64 / 256
        size_t i = (size_t)bid * 256 + tid;
        __half hi, lo;
        split_h(x[i], hi, lo);
        g_xhi[i] = hi;
        g_xlo[i] = lo;
    } else if (bid < 32768 + 128) {          // W1^T: 512*64 / 256
        int i = (bid - 32768) * 256 + tid;
        int n = i >> 6, k = i & 63;
        __half hi, lo;
        split_h(W1[k * 512 + n], hi, lo);
        g_w1hi[i] = hi;
        g_w1lo[i] = lo;
    } else {                                 // W2^T*eta: 512*512 / 256
        int i = (bid - 32896) * 256 + tid;
        int n = i >> 9, k = i & 511;
        __half hi, lo;
        split_h(W2[k * 513 + n] * eta[0], hi, lo);
        g_w2hi[i] = hi;
        g_w2lo[i] = lo;
    }
}

#define LDSM_X4(r0, r1, r2, r3, addr)                                        \
    asm volatile(                                                            \
        "ldmatrix.sync.aligned.m8n8.x4.shared.b16 {%0,%1,%2,%3}, [%4];"      \
        : "=r"(r0), "=r"(r1), "=r"(r2), "=r"(r3) : "r"(addr))

#define MMA16816(d, a, b)                                                    \
    asm volatile(                                                            \
        "mma.sync.aligned.m16n8k16.row.col.f32.f16.f16.f32 "                 \
        "{%0,%1,%2,%3}, {%4,%5,%6,%7}, {%8,%9}, {%0,%1,%2,%3};"              \
        : "+f"((d)[0]), "+f"((d)[1]), "+f"((d)[2]), "+f"((d)[3])             \
        : "r"((a)[0]), "r"((a)[1]), "r"((a)[2]), "r"((a)[3]),                \
          "r"((b)[0]), "r"((b)[1]))

// one fused hi/lo k32 chunk load (smem row = [hi 64B | lo 64B], XOR swizzle)
#define LOADC(AH, AL, BH, BL, SSTR, blockRow, colbase, kc, buf)              \
    do {                                                                     \
        const char* ah_ = (const char*)(AH) + (size_t)(blockRow) * (SSTR) +  \
                          (size_t)(kc) * 64;                                 \
        const char* al_ = (const char*)(AL) + (size_t)(blockRow) * (SSTR) +  \
                          (size_t)(kc) * 64;                                 \
        const char* bh_ = (const char*)(BH) + (size_t)(colbase) * (SSTR) +   \
                          (size_t)(kc) * 64;                                 \
        const char* bl_ = (const char*)(BL) + (size_t)(colbase) * (SSTR) +   \
                          (size_t)(kc) * 64;                                 \
        uint32_t ab_ = sbase + (uint32_t)(buf) * 32768u;                     \
        uint32_t bb_ = ab_ + 16384u;                                         \
        _Pragma("unroll")                                                    \
        for (int j_ = 0; j_ < 4; j_++) {                                     \
            int gi_ = tid + 256 * j_;                                        \
            int row_ = gi_ >> 3, u_ = gi_ & 7;                               \
            const char* src_ = ((u_ < 4) ? ah_ : al_) +                      \
                               (size_t)row_ * (SSTR) + (u_ & 3) * 16;        \
            uint32_t dst_ = ab_ + row_ * 128u +                              \
                            (uint32_t)((u_ ^ (row_ & 7)) << 4);              \
            asm volatile("cp.async.cg.shared.global [%0], [%1], 16;"         \
                         :: "r"(dst_), "l"(src_));                           \
        }                                                                    \
        _Pragma("unroll")                                                    \
        for (int j_ = 0; j_ < 4; j_++) {                                     \
            int gi_ = tid + 256 * j_;                                        \
            int row_ = gi_ >> 3, u_ = gi_ & 7;                               \
            const char* src_ = ((u_ < 4) ? bh_ : bl_) +                      \
                               (size_t)row_ * (SSTR) + (u_ & 3) * 16;        \
            uint32_t dst_ = bb_ + row_ * 128u +                              \
                            (uint32_t)((u_ ^ (row_ & 7)) << 4);              \
            asm volatile("cp.async.cg.shared.global [%0], [%1], 16;"         \
                         :: "r"(dst_), "l"(src_));                           \
        }                                                                    \
        asm volatile("cp.async.commit_group;");                              \
    } while (0)

// one k32 fused-chunk compute: 3 products x 2 k16 steps into acc[2][8][4]
#define CHUNK_MMA(buf)                                                       \
    do {                                                                     \
        uint32_t ab_ = sbase + (uint32_t)(buf) * 32768u;                     \
        uint32_t bb_ = ab_ + 16384u;                                         \
        _Pragma("unroll")                                                    \
        for (int kk = 0; kk < 2; kk++) {                                     \
            uint32_t a_hi[2][4], a_lo[2][4];                                 \
            uint32_t b_hi[8][2], b_lo[8][2];                                 \
            _Pragma("unroll")                                                \
            for (int mi = 0; mi < 2; mi++) {                                 \
                int row = aRow + mi * 16;                                    \
                uint32_t ah_ = ab_ + row * 128u +                            \
                               (uint32_t)(((kk * 2 + aU) ^ aX) << 4);        \
                LDSM_X4(a_hi[mi][0], a_hi[mi][1], a_hi[mi][2], a_hi[mi][3],  \
                        ah_);                                                \
            }                                                                \
            _Pragma("unroll")                                                \
            for (int p = 0; p < 4; p++) {                                    \
                int row = bRow + p * 16;                                     \
                uint32_t bh_ = bb_ + row * 128u +                            \
                               (uint32_t)(((kk * 2 + bU) ^ bX) << 4);        \
                LDSM_X4(b_hi[2 * p][0], b_hi[2 * p][1],                      \
                        b_hi[2 * p + 1][0], b_hi[2 * p + 1][1], bh_);        \
            }                                                                \
            _Pragma("unroll")                                                \
            for (int mi = 0; mi < 2; mi++) {                                 \
                int row = aRow + mi * 16;                                    \
                uint32_t al_ = ab_ + row * 128u +                            \
                               (uint32_t)(((4 + kk * 2 + aU) ^ aX) << 4);    \
                LDSM_X4(a_lo[mi][0], a_lo[mi][1], a_lo[mi][2], a_lo[mi][3],  \
                        al_);                                                \
            }                                                                \
            _Pragma("unroll")                                                \
            for (int mi = 0; mi < 2; mi++)                                   \
                _Pragma("unroll")                                            \
                for (int nj = 0; nj < 8; nj++)                               \
                    MMA16816(acc[mi][nj], a_hi[mi], b_hi[nj]);               \
            _Pragma("unroll")                                                \
            for (int p = 0; p < 4; p++) {                                    \
                int row = bRow + p * 16;                                     \
                uint32_t bl_ = bb_ + row * 128u +                            \
                               (uint32_t)(((4 + kk * 2 + bU) ^ bX) << 4);    \
                LDSM_X4(b_lo[2 * p][0], b_lo[2 * p][1],                      \
                        b_lo[2 * p + 1][0], b_lo[2 * p + 1][1], bl_);        \
            }                                                                \
            _Pragma("unroll")                                                \
            for (int mi = 0; mi < 2; mi++)                                   \
                _Pragma("unroll")                                            \
                for (int nj = 0; nj < 8; nj++)                               \
                    MMA16816(acc[mi][nj], a_lo[mi], b_hi[nj]);               \
            _Pragma("unroll")                                                \
            for (int mi = 0; mi < 2; mi++)                                   \
                _Pragma("unroll")                                            \
                for (int nj = 0; nj < 8; nj++)                               \
                    MMA16816(acc[mi][nj], a_hi[mi], b_lo[nj]);               \
        }                                                                    \
    } while (0)

#define THREAD_SETUP()                                                       \
    const int tid = threadIdx.x;                                             \
    const int lane = tid & 31;                                               \
    const int wid = tid >> 5;                                                \
    const int wm = (wid & 3) * 32;                                           \
    const int wn = (wid >> 2) * 64;                                          \
    const int aRow = wm + (lane & 7) + ((lane >> 3) & 1) * 8;                \
    const int aU = (lane >> 4) & 1;                                          \
    const int aX = aRow & 7;                                                 \
    const int bRow = wn + (lane & 7) + ((lane >> 4) & 1) * 8;                \
    const int bU = (lane >> 3) & 1;                                          \
    const int bX = bRow & 7;                                                 \
    const int g = lane >> 2;                                                 \
    const int tig = lane & 3;                                                \
    float acc[2][8][4];                                                      \
    _Pragma("unroll")                                                        \
    for (int mi = 0; mi < 2; mi++)                                           \
        _Pragma("unroll")                                                    \
        for (int nj = 0; nj < 8; nj++)                                       \
            _Pragma("unroll")                                                \
            for (int q = 0; q < 4; q++) acc[mi][nj][q] = 0.0f;

// ---------------------------------------------------------------------------
// PHASE 1: h = relu(x@W1+b1) + fp16 split. Per-job grid (4, 1024).
// ---------------------------------------------------------------------------
__global__ __launch_bounds__(256, 2)
void mma_phase1_kernel(const float* __restrict__ b1) {
    extern __shared__ char smem[];
    const uint32_t sbase = (uint32_t)__cvta_generic_to_shared(smem);
    THREAD_SETUP();
    const int blockRow = blockIdx.y * 128;
    const int colbase = blockIdx.x * 128;
    constexpr int SSTR = 128;

    LOADC(g_xhi, g_xlo, g_w1hi, g_w1lo, SSTR, blockRow, colbase, 0, 0);
    LOADC(g_xhi, g_xlo, g_w1hi, g_w1lo, SSTR, blockRow, colbase, 1, 1);
    asm volatile("cp.async.wait_group 1;");
    __syncthreads();
    CHUNK_MMA(0);
    asm volatile("cp.async.wait_group 0;");
    __syncthreads();
    CHUNK_MMA(1);

    __half* s_hi = reinterpret_cast<__half*>(smem);             // 128x136
    __half* s_lo = reinterpret_cast<__half*>(smem + 128 * 272); // 128x136
    __syncthreads();
#pragma unroll
    for (int mi = 0; mi < 2; mi++)
#pragma unroll
        for (int rsel = 0; rsel < 2; rsel++) {
            int rloc = wm + mi * 16 + g + rsel * 8;
#pragma unroll
            for (int nj = 0; nj < 8; nj++) {
                int cloc = wn + nj * 8 + 2 * tig;
                int cc = colbase + cloc;
                float h0 = fmaxf(acc[mi][nj][rsel * 2 + 0] + b1[cc], 0.0f);
                float h1 = fmaxf(acc[mi][nj][rsel * 2 + 1] + b1[cc + 1], 0.0f);
                __half hi0, lo0, hi1, lo1;
                split_h(h0, hi0, lo0);
                split_h(h1, hi1, lo1);
                *reinterpret_cast<__half2*>(&s_hi[rloc * 136 + cloc]) =
                    __halves2half2(hi0, hi1);
                *reinterpret_cast<__half2*>(&s_lo[rloc * 136 + cloc]) =
                    __halves2half2(lo0, lo1);
            }
        }
    __syncthreads();
#pragma unroll
    for (int it = 0; it < 8; it++) {
        int idx = tid + it * 256;
        int row = idx >> 4, seg = idx & 15;
        uint4 v = *reinterpret_cast<uint4*>(&s_hi[row * 136 + seg * 8]);
        *reinterpret_cast<uint4*>(
            &g_hhi[(size_t)(blockRow + row) * 512 + colbase + seg * 8]) = v;
        uint4 w = *reinterpret_cast<uint4*>(&s_lo[row * 136 + seg * 8]);
        *reinterpret_cast<uint4*>(
            &g_hlo[(size_t)(blockRow + row) * 512 + colbase + seg * 8]) = w;
    }
}

// ---------------------------------------------------------------------------
// PHASE 2: params = h@(W2*eta) + Moebius. Per-job grid (4, 1024).
// Leading cp.async group prefetches theta/r/b2 slices to smem so the
// epilogue reads are smem hits (removes exposed scattered LDGs).
// ---------------------------------------------------------------------------
__global__ __launch_bounds__(256, 2)
void mma_phase2_kernel(const float* __restrict__ b2,
                       const float* __restrict__ theta,
                       const float* __restrict__ r_in,
                       const float* __restrict__ eta,
                       float* __restrict__ out) {
    extern __shared__ char smem[];
    const uint32_t sbase = (uint32_t)__cvta_generic_to_shared(smem);
    THREAD_SETUP();
    const int blockRow = blockIdx.y * 128;
    const int colbase = blockIdx.x * 128;
    constexpr int SSTR = 1024;
    constexpr int NC = 16;

    float* s_th = reinterpret_cast<float*>(smem + 98304);          // 128x12
    float* s_rr = reinterpret_cast<float*>(smem + 98304 + 6144);   // 128x12
    float* s_b2 = reinterpret_cast<float*>(smem + 98304 + 12288);  // 128

    // G0: theta/r (32B per row, this col-quarter's 8 dims) + bias slice
    {
        int row = tid >> 1, seg = tid & 1;
        const char* st = (const char*)theta + (size_t)(blockRow + row) * 128 +
                         blockIdx.x * 32 + seg * 16;
        uint32_t dt = sbase + 98304u + row * 48u + seg * 16u;
        asm volatile("cp.async.ca.shared.global [%0], [%1], 16;"
                     :: "r"(dt), "l"(st));
        const char* sr = (const char*)r_in + (size_t)(blockRow + row) * 128 +
                         blockIdx.x * 32 + seg * 16;
        uint32_t dr = sbase + 98304u + 6144u + row * 48u + seg * 16u;
        asm volatile("cp.async.ca.shared.global [%0], [%1], 16;"
                     :: "r"(dr), "l"(sr));
        if (tid < 32) {
            const char* sb = (const char*)b2 + colbase * 4 + tid * 16;
            uint32_t db = sbase + 98304u + 12288u + tid * 16u;
            asm volatile("cp.async.ca.shared.global [%0], [%1], 16;"
                         :: "r"(db), "l"(sb));
        }
        asm volatile("cp.async.commit_group;");
    }

    LOADC(g_hhi, g_hlo, g_w2hi, g_w2lo, SSTR, blockRow, colbase, 0, 0);
    LOADC(g_hhi, g_hlo, g_w2hi, g_w2lo, SSTR, blockRow, colbase, 1, 1);
    asm volatile("cp.async.wait_group 1;");   // G0 + chunk0 done
    __syncthreads();

#pragma unroll 1
    for (int c = 0; c < NC; c++) {
        if (c + 2 < NC) {
            int kc = c + 2;
            LOADC(g_hhi, g_hlo, g_w2hi, g_w2lo, SSTR, blockRow, colbase,
                  kc, kc % 3);
        } else {
            asm volatile("cp.async.commit_group;");
        }
        CHUNK_MMA(c % 3);
        asm volatile("cp.async.wait_group 1;");
        __syncthreads();
    }

    // ---- Moebius epilogue (theta/r/bias from smem) ----
    const float e = eta[0];
    float bb2[8][2];
#pragma unroll
    for (int nj = 0; nj < 8; nj++) {
        int cl = wn + nj * 8 + 2 * tig;
        bb2[nj][0] = s_b2[cl] * e;
        bb2[nj][1] = s_b2[cl + 1] * e;
    }
    const int d0c = colbase >> 4;
    const int dbloc = wn >> 4;          // 0 or 4
    float* s_out = reinterpret_cast<float*>(smem);   // 128x17, overlays chunks

#pragma unroll
    for (int mi = 0; mi < 2; mi++)
#pragma unroll
        for (int rsel = 0; rsel < 2; rsel++) {
            int rloc = wm + mi * 16 + g + rsel * 8;
#pragma unroll
            for (int dj = 0; dj < 4; dj++) {
                int dl = dbloc + dj;
                float th = s_th[rloc * 12 + dl];
                float rr = s_rr[rloc * 12 + dl];
                float sn, cs;
                sincosf(th, &sn, &cs);
                float z0 = rr * cs, z1 = rr * sn;
                float rr2 = rr * rr;
                float sumT = 0.0f, sumS = 0.0f;
#pragma unroll
                for (int hf = 0; hf < 2; hf++) {
                    int nj = 2 * dj + hf;
                    float p0 = acc[mi][nj][rsel * 2 + 0] + bb2[nj][0];
                    float p1 = acc[mi][nj][rsel * 2 + 1] + bb2[nj][1];
                    float nrm = sqrtf(p0 * p0 + p1 * p1);
                    float f = rr * 0.99f / (1.0f + nrm);
                    float w0 = f * p0, w1 = f * p1;
                    float zw0 = z0 - w0, zw1 = z1 - w1;
                    float dist2 = zw0 * zw0 + zw1 * zw1;
                    float scale = (rr2 - (w0 * w0 + w1 * w1)) / dist2;
                    float zo0 = scale * zw0 - w0;
                    float zo1 = scale * zw1 - w1;
                    float ang = atan2f(zo1, zo0);
                    if (ang < 0.0f) ang += TWO_PI_F;
                    sumT += ang;
                    sumS += scale;
                }
                sumT += __shfl_xor_sync(0xffffffffu, sumT, 1);
                sumS += __shfl_xor_sync(0xffffffffu, sumS, 1);
                sumT += __shfl_xor_sync(0xffffffffu, sumT, 2);
                sumS += __shfl_xor_sync(0xffffffffu, sumS, 2);
                if (tig == 0) {
                    s_out[rloc * 17 + dl] = sumT * 0.125f;
                    s_out[rloc * 17 + 8 + dl] = logf(sumS * 0.125f + 1e-8f);
                }
            }
        }
    __syncthreads();
#pragma unroll
    for (int it = 0; it < 8; it++) {
        int idx = tid + it * 256;
        int row = idx >> 4;
        int rest = idx & 15;
        int t = rest >> 3;
        int dl = rest & 7;
        float v = s_out[row * 17 + t * 8 + dl];
        out[(size_t)t * B_TOTAL * DH + (size_t)(blockRow + row) * DH +
            d0c + dl] = v;
    }
}

// ---------------- launch ----------------
extern "C" void kernel_launch(void* const* d_in, const int* in_sizes, int n_in,
                              void* d_out, int out_size) {
    const float* theta = (const float*)d_in[0];
    const float* r     = (const float*)d_in[1];
    const float* x     = (const float*)d_in[2];
    const float* W1    = (const float*)d_in[3];
    const float* W2    = (const float*)d_in[5];
    const float* b1    = (const float*)d_in[4];
    const float* b2    = (const float*)d_in[6];
    const float* eta   = (const float*)d_in[7];
    float* out = (float*)d_out;

    pack_all_kernel<<<32768 + 128 + 1024, 256>>>(x, W1, W2, eta);

    const int smem1 = 128 * 272 * 2;                    // 69632 B
    const int smem2 = 98304 + 6144 + 6144 + 512;        // 111104 B
    cudaFuncSetAttribute(mma_phase1_kernel,
                         cudaFuncAttributeMaxDynamicSharedMemorySize, smem1);
    cudaFuncSetAttribute(mma_phase2_kernel,
                         cudaFuncAttributeMaxDynamicSharedMemorySize, smem2);

    dim3 grid(4, B_TOTAL / 128);
    mma_phase1_kernel<<<grid, 256, smem1>>>(b1);
    mma_phase2_kernel<<<grid, 256, smem2>>>(b2, theta, r, eta, out);
}

// round 15
// speedup vs baseline: 1.1264x; 1.0483x over previous
#include <cuda_runtime.h>
#include <cuda_fp16.h>
#include <math.h>
#include <stdint.h>

// ---------------- problem constants ----------------
#define B_TOTAL   131072
#define DH        32
#define TWO_PI_F  6.283185307179586f

// ---------------- device scratch (static, no alloc) ----------------
__device__ __half g_xhi[(size_t)B_TOTAL * 64];
__device__ __half g_xlo[(size_t)B_TOTAL * 64];
__device__ __half g_hhi[(size_t)B_TOTAL * 512];
__device__ __half g_hlo[(size_t)B_TOTAL * 512];
__device__ __half g_w1hi[512 * 64];    // W1^T [n=512][k=64]
__device__ __half g_w1lo[512 * 64];
__device__ __half g_w2hi[512 * 512];   // (W2*eta)^T [n=512][k=512]
__device__ __half g_w2lo[512 * 512];

__device__ __forceinline__ void split_h(float v, __half& hi, __half& lo) {
    hi = __float2half_rn(v);
    lo = __float2half_rn(v - __half2float(hi));
}

// ---------------- combined pack kernel (x4 vectorized) ----------------
__global__ void pack_all_kernel(const float* __restrict__ x,
                                const float* __restrict__ W1,
                                const float* __restrict__ W2,
                                const float* __restrict__ eta) {
    int bid = blockIdx.x, tid = threadIdx.x;
    if (bid < 8192) {                        // x: B*64 elems, 4 per thread
        size_t i4 = ((size_t)bid * 256 + tid) * 4;
        float4 v = *reinterpret_cast<const float4*>(x + i4);
        __half h0, l0, h1, l1, h2, l2, h3, l3;
        split_h(v.x, h0, l0);
        split_h(v.y, h1, l1);
        split_h(v.z, h2, l2);
        split_h(v.w, h3, l3);
        *reinterpret_cast<__half2*>(&g_xhi[i4])     = __halves2half2(h0, h1);
        *reinterpret_cast<__half2*>(&g_xhi[i4 + 2]) = __halves2half2(h2, h3);
        *reinterpret_cast<__half2*>(&g_xlo[i4])     = __halves2half2(l0, l1);
        *reinterpret_cast<__half2*>(&g_xlo[i4 + 2]) = __halves2half2(l2, l3);
    } else if (bid < 8192 + 32) {            // W1^T: 512*64, 4 k per thread
        int q = ((bid - 8192) * 256 + tid) * 4;
        int n = q >> 6, k = q & 63;
#pragma unroll
        for (int j = 0; j < 4; j++) {
            __half hi, lo;
            split_h(W1[(k + j) * 512 + n], hi, lo);
            g_w1hi[n * 64 + k + j] = hi;
            g_w1lo[n * 64 + k + j] = lo;
        }
    } else {                                 // W2^T*eta: 512*512, 4 k per thread
        int q = ((bid - 8224) * 256 + tid) * 4;
        int n = q >> 9, k = q & 511;
        float e = eta[0];
#pragma unroll
        for (int j = 0; j < 4; j++) {
            __half hi, lo;
            split_h(W2[(k + j) * 513 + n] * e, hi, lo);
            g_w2hi[n * 512 + k + j] = hi;
            g_w2lo[n * 512 + k + j] = lo;
        }
    }
}

#define LDSM_X4(r0, r1, r2, r3, addr)                                        \
    asm volatile(                                                            \
        "ldmatrix.sync.aligned.m8n8.x4.shared.b16 {%0,%1,%2,%3}, [%4];"      \
        : "=r"(r0), "=r"(r1), "=r"(r2), "=r"(r3) : "r"(addr))

#define MMA16816(d, a, b)                                                    \
    asm volatile(                                                            \
        "mma.sync.aligned.m16n8k16.row.col.f32.f16.f16.f32 "                 \
        "{%0,%1,%2,%3}, {%4,%5,%6,%7}, {%8,%9}, {%0,%1,%2,%3};"              \
        : "+f"((d)[0]), "+f"((d)[1]), "+f"((d)[2]), "+f"((d)[3])             \
        : "r"((a)[0]), "r"((a)[1]), "r"((a)[2]), "r"((a)[3]),                \
          "r"((b)[0]), "r"((b)[1]))

// ===================== PHASE 1 (unchanged champion: N=128, 2 CTAs/SM) ======
#define LOADC1(AH, AL, BH, BL, SSTR, blockRow, colbase, kc, buf)             \
    do {                                                                     \
        const char* ah_ = (const char*)(AH) + (size_t)(blockRow) * (SSTR) +  \
                          (size_t)(kc) * 64;                                 \
        const char* al_ = (const char*)(AL) + (size_t)(blockRow) * (SSTR) +  \
                          (size_t)(kc) * 64;                                 \
        const char* bh_ = (const char*)(BH) + (size_t)(colbase) * (SSTR) +   \
                          (size_t)(kc) * 64;                                 \
        const char* bl_ = (const char*)(BL) + (size_t)(colbase) * (SSTR) +   \
                          (size_t)(kc) * 64;                                 \
        uint32_t ab_ = sbase + (uint32_t)(buf) * 32768u;                     \
        uint32_t bb_ = ab_ + 16384u;                                         \
        _Pragma("unroll")                                                    \
        for (int j_ = 0; j_ < 4; j_++) {                                     \
            int gi_ = tid + 256 * j_;                                        \
            int row_ = gi_ >> 3, u_ = gi_ & 7;                               \
            const char* src_ = ((u_ < 4) ? ah_ : al_) +                      \
                               (size_t)row_ * (SSTR) + (u_ & 3) * 16;        \
            uint32_t dst_ = ab_ + row_ * 128u +                              \
                            (uint32_t)((u_ ^ (row_ & 7)) << 4);              \
            asm volatile("cp.async.cg.shared.global [%0], [%1], 16;"         \
                         :: "r"(dst_), "l"(src_));                           \
        }                                                                    \
        _Pragma("unroll")                                                    \
        for (int j_ = 0; j_ < 4; j_++) {                                     \
            int gi_ = tid + 256 * j_;                                        \
            int row_ = gi_ >> 3, u_ = gi_ & 7;                               \
            const char* src_ = ((u_ < 4) ? bh_ : bl_) +                      \
                               (size_t)row_ * (SSTR) + (u_ & 3) * 16;        \
            uint32_t dst_ = bb_ + row_ * 128u +                              \
                            (uint32_t)((u_ ^ (row_ & 7)) << 4);              \
            asm volatile("cp.async.cg.shared.global [%0], [%1], 16;"         \
                         :: "r"(dst_), "l"(src_));                           \
        }                                                                    \
        asm volatile("cp.async.commit_group;");                              \
    } while (0)

#define CHUNK_MMA1(buf)                                                      \
    do {                                                                     \
        uint32_t ab_ = sbase + (uint32_t)(buf) * 32768u;                     \
        uint32_t bb_ = ab_ + 16384u;                                         \
        _Pragma("unroll")                                                    \
        for (int kk = 0; kk < 2; kk++) {                                     \
            uint32_t a_hi[2][4], a_lo[2][4];                                 \
            uint32_t b_hi[8][2], b_lo[8][2];                                 \
            _Pragma("unroll")                                                \
            for (int mi = 0; mi < 2; mi++) {                                 \
                int row = aRow + mi * 16;                                    \
                uint32_t ah_ = ab_ + row * 128u +                            \
                               (uint32_t)(((kk * 2 + aU) ^ aX) << 4);        \
                LDSM_X4(a_hi[mi][0], a_hi[mi][1], a_hi[mi][2], a_hi[mi][3],  \
                        ah_);                                                \
            }                                                                \
            _Pragma("unroll")                                                \
            for (int p = 0; p < 4; p++) {                                    \
                int row = bRow + p * 16;                                     \
                uint32_t bh_ = bb_ + row * 128u +                            \
                               (uint32_t)(((kk * 2 + bU) ^ bX) << 4);        \
                LDSM_X4(b_hi[2 * p][0], b_hi[2 * p][1],                      \
                        b_hi[2 * p + 1][0], b_hi[2 * p + 1][1], bh_);        \
            }                                                                \
            _Pragma("unroll")                                                \
            for (int mi = 0; mi < 2; mi++) {                                 \
                int row = aRow + mi * 16;                                    \
                uint32_t al_ = ab_ + row * 128u +                            \
                               (uint32_t)(((4 + kk * 2 + aU) ^ aX) << 4);    \
                LDSM_X4(a_lo[mi][0], a_lo[mi][1], a_lo[mi][2], a_lo[mi][3],  \
                        al_);                                                \
            }                                                                \
            _Pragma("unroll")                                                \
            for (int mi = 0; mi < 2; mi++)                                   \
                _Pragma("unroll")                                            \
                for (int nj = 0; nj < 8; nj++)                               \
                    MMA16816(acc[mi][nj], a_hi[mi], b_hi[nj]);               \
            _Pragma("unroll")                                                \
            for (int p = 0; p < 4; p++) {                                    \
                int row = bRow + p * 16;                                     \
                uint32_t bl_ = bb_ + row * 128u +                            \
                               (uint32_t)(((4 + kk * 2 + bU) ^ bX) << 4);    \
                LDSM_X4(b_lo[2 * p][0], b_lo[2 * p][1],                      \
                        b_lo[2 * p + 1][0], b_lo[2 * p + 1][1], bl_);        \
            }                                                                \
            _Pragma("unroll")                                                \
            for (int mi = 0; mi < 2; mi++)                                   \
                _Pragma("unroll")                                            \
                for (int nj = 0; nj < 8; nj++)                               \
                    MMA16816(acc[mi][nj], a_lo[mi], b_hi[nj]);               \
            _Pragma("unroll")                                                \
            for (int mi = 0; mi < 2; mi++)                                   \
                _Pragma("unroll")                                            \
                for (int nj = 0; nj < 8; nj++)                               \
                    MMA16816(acc[mi][nj], a_hi[mi], b_lo[nj]);               \
        }                                                                    \
    } while (0)

__global__ __launch_bounds__(256, 2)
void mma_phase1_kernel(const float* __restrict__ b1) {
    extern __shared__ char smem[];
    const uint32_t sbase = (uint32_t)__cvta_generic_to_shared(smem);
    const int tid = threadIdx.x;
    const int lane = tid & 31;
    const int wid = tid >> 5;
    const int wm = (wid & 3) * 32;
    const int wn = (wid >> 2) * 64;
    const int aRow = wm + (lane & 7) + ((lane >> 3) & 1) * 8;
    const int aU = (lane >> 4) & 1;
    const int aX = aRow & 7;
    const int bRow = wn + (lane & 7) + ((lane >> 4) & 1) * 8;
    const int bU = (lane >> 3) & 1;
    const int bX = bRow & 7;
    const int g = lane >> 2;
    const int tig = lane & 3;
    float acc[2][8][4];
#pragma unroll
    for (int mi = 0; mi < 2; mi++)
#pragma unroll
        for (int nj = 0; nj < 8; nj++)
#pragma unroll
            for (int q = 0; q < 4; q++) acc[mi][nj][q] = 0.0f;

    const int blockRow = blockIdx.y * 128;
    const int colbase = blockIdx.x * 128;
    constexpr int SSTR = 128;

    LOADC1(g_xhi, g_xlo, g_w1hi, g_w1lo, SSTR, blockRow, colbase, 0, 0);
    LOADC1(g_xhi, g_xlo, g_w1hi, g_w1lo, SSTR, blockRow, colbase, 1, 1);
    asm volatile("cp.async.wait_group 1;");
    __syncthreads();
    CHUNK_MMA1(0);
    asm volatile("cp.async.wait_group 0;");
    __syncthreads();
    CHUNK_MMA1(1);

    __half* s_hi = reinterpret_cast<__half*>(smem);             // 128x136
    __half* s_lo = reinterpret_cast<__half*>(smem + 128 * 272); // 128x136
    __syncthreads();
#pragma unroll
    for (int mi = 0; mi < 2; mi++)
#pragma unroll
        for (int rsel = 0; rsel < 2; rsel++) {
            int rloc = wm + mi * 16 + g + rsel * 8;
#pragma unroll
            for (int nj = 0; nj < 8; nj++) {
                int cloc = wn + nj * 8 + 2 * tig;
                int cc = colbase + cloc;
                float h0 = fmaxf(acc[mi][nj][rsel * 2 + 0] + b1[cc], 0.0f);
                float h1 = fmaxf(acc[mi][nj][rsel * 2 + 1] + b1[cc + 1], 0.0f);
                __half hi0, lo0, hi1, lo1;
                split_h(h0, hi0, lo0);
                split_h(h1, hi1, lo1);
                *reinterpret_cast<__half2*>(&s_hi[rloc * 136 + cloc]) =
                    __halves2half2(hi0, hi1);
                *reinterpret_cast<__half2*>(&s_lo[rloc * 136 + cloc]) =
                    __halves2half2(lo0, lo1);
            }
        }
    __syncthreads();
#pragma unroll
    for (int it = 0; it < 8; it++) {
        int idx = tid + it * 256;
        int row = idx >> 4, seg = idx & 15;
        uint4 v = *reinterpret_cast<uint4*>(&s_hi[row * 136 + seg * 8]);
        *reinterpret_cast<uint4*>(
            &g_hhi[(size_t)(blockRow + row) * 512 + colbase + seg * 8]) = v;
        uint4 w = *reinterpret_cast<uint4*>(&s_lo[row * 136 + seg * 8]);
        *reinterpret_cast<uint4*>(
            &g_hlo[(size_t)(blockRow + row) * 512 + colbase + seg * 8]) = w;
    }
}

// ===================== PHASE 2: N=64 tile, 3 CTAs/SM (6 warps/SMSP) ========
// CTA 256 thr, tile M128 x N64; warp grid 4(m) x 2(n), warp tile 32x32 ->
// acc[2][4][4] (32 regs). Chunks: A 16KB + B 8KB = 24KB, 3 stages (72KB/CTA).
// Product order frees b_hi before b_lo loads (peak live frags = 24 regs).
// Grid (8, 1024) x-fast: 8 row-sharing CTAs adjacent -> A L2-hot.
__global__ __launch_bounds__(256, 3)
void mma_phase2_kernel(const float* __restrict__ b2,
                       const float* __restrict__ theta,
                       const float* __restrict__ r_in,
                       const float* __restrict__ eta,
                       float* __restrict__ out) {
    extern __shared__ char smem[];
    const uint32_t sbase = (uint32_t)__cvta_generic_to_shared(smem);
    const int tid = threadIdx.x;
    const int lane = tid & 31;
    const int wid = tid >> 5;
    const int wm = (wid & 3) * 32;
    const int wn = (wid >> 2) * 32;        // 0 or 32
    const int aRow = wm + (lane & 7) + ((lane >> 3) & 1) * 8;
    const int aU = (lane >> 4) & 1;
    const int aX = aRow & 7;
    const int bRow = wn + (lane & 7) + ((lane >> 4) & 1) * 8;
    const int bU = (lane >> 3) & 1;
    const int bX = bRow & 7;
    const int g = lane >> 2;
    const int tig = lane & 3;

    const int blockRow = blockIdx.y * 128;
    const int colbase = blockIdx.x * 64;
    constexpr int SSTR = 1024;
    constexpr int NC = 16;
    constexpr uint32_t CHUNK = 24576u;     // A 16KB + B 8KB

    float acc[2][4][4];
#pragma unroll
    for (int mi = 0; mi < 2; mi++)
#pragma unroll
        for (int nj = 0; nj < 4; nj++)
#pragma unroll
            for (int q = 0; q < 4; q++) acc[mi][nj][q] = 0.0f;

    // chunk loader: A 4 units/thread, B 2 units/thread
#define LOADC2(kc, buf)                                                      \
    do {                                                                     \
        const char* ah_ = (const char*)g_hhi +                               \
                          (size_t)blockRow * SSTR + (size_t)(kc) * 64;       \
        const char* al_ = (const char*)g_hlo +                               \
                          (size_t)blockRow * SSTR + (size_t)(kc) * 64;       \
        const char* bh_ = (const char*)g_w2hi +                              \
                          (size_t)colbase * SSTR + (size_t)(kc) * 64;        \
        const char* bl_ = (const char*)g_w2lo +                              \
                          (size_t)colbase * SSTR + (size_t)(kc) * 64;        \
        uint32_t ab_ = sbase + (uint32_t)(buf) * CHUNK;                      \
        uint32_t bb_ = ab_ + 16384u;                                         \
        _Pragma("unroll")                                                    \
        for (int j_ = 0; j_ < 4; j_++) {                                     \
            int gi_ = tid + 256 * j_;                                        \
            int row_ = gi_ >> 3, u_ = gi_ & 7;                               \
            const char* src_ = ((u_ < 4) ? ah_ : al_) +                      \
                               (size_t)row_ * SSTR + (u_ & 3) * 16;          \
            uint32_t dst_ = ab_ + row_ * 128u +                              \
                            (uint32_t)((u_ ^ (row_ & 7)) << 4);              \
            asm volatile("cp.async.cg.shared.global [%0], [%1], 16;"         \
                         :: "r"(dst_), "l"(src_));                           \
        }                                                                    \
        _Pragma("unroll")                                                    \
        for (int j_ = 0; j_ < 2; j_++) {                                     \
            int gi_ = tid + 256 * j_;                                        \
            int row_ = gi_ >> 3, u_ = gi_ & 7;                               \
            const char* src_ = ((u_ < 4) ? bh_ : bl_) +                      \
                               (size_t)row_ * SSTR + (u_ & 3) * 16;          \
            uint32_t dst_ = bb_ + row_ * 128u +                              \
                            (uint32_t)((u_ ^ (row_ & 7)) << 4);              \
            asm volatile("cp.async.cg.shared.global [%0], [%1], 16;"         \
                         :: "r"(dst_), "l"(src_));                           \
        }                                                                    \
        asm volatile("cp.async.commit_group;");                              \
    } while (0)

    LOADC2(0, 0);
    LOADC2(1, 1);
    asm volatile("cp.async.wait_group 1;");
    __syncthreads();

#pragma unroll 1
    for (int c = 0; c < NC; c++) {
        if (c + 2 < NC) {
            int kc = c + 2;
            LOADC2(kc, kc % 3);
        } else {
            asm volatile("cp.async.commit_group;");
        }

        uint32_t ab_ = sbase + (uint32_t)(c % 3) * CHUNK;
        uint32_t bb_ = ab_ + 16384u;
#pragma unroll
        for (int kk = 0; kk < 2; kk++) {
            uint32_t a_hi[2][4], a_lo[2][4], b[4][2];
#pragma unroll
            for (int mi = 0; mi < 2; mi++) {
                int row = aRow + mi * 16;
                uint32_t ad = ab_ + row * 128u +
                              (uint32_t)(((kk * 2 + aU) ^ aX) << 4);
                LDSM_X4(a_hi[mi][0], a_hi[mi][1], a_hi[mi][2], a_hi[mi][3], ad);
            }
#pragma unroll
            for (int p = 0; p < 2; p++) {       // b_hi
                int row = bRow + p * 16;
                uint32_t bd = bb_ + row * 128u +
                              (uint32_t)(((kk * 2 + bU) ^ bX) << 4);
                LDSM_X4(b[2 * p][0], b[2 * p][1],
                        b[2 * p + 1][0], b[2 * p + 1][1], bd);
            }
#pragma unroll
            for (int mi = 0; mi < 2; mi++) {
                int row = aRow + mi * 16;
                uint32_t ad = ab_ + row * 128u +
                              (uint32_t)(((4 + kk * 2 + aU) ^ aX) << 4);
                LDSM_X4(a_lo[mi][0], a_lo[mi][1], a_lo[mi][2], a_lo[mi][3], ad);
            }
            // P1: a_hi * b_hi
#pragma unroll
            for (int mi = 0; mi < 2; mi++)
#pragma unroll
                for (int nj = 0; nj < 4; nj++)
                    MMA16816(acc[mi][nj], a_hi[mi], b[nj]);
            // P2: a_lo * b_hi (b_hi dead after)
#pragma unroll
            for (int mi = 0; mi < 2; mi++)
#pragma unroll
                for (int nj = 0; nj < 4; nj++)
                    MMA16816(acc[mi][nj], a_lo[mi], b[nj]);
            // reload b := b_lo
#pragma unroll
            for (int p = 0; p < 2; p++) {
                int row = bRow + p * 16;
                uint32_t bd = bb_ + row * 128u +
                              (uint32_t)(((4 + kk * 2 + bU) ^ bX) << 4);
                LDSM_X4(b[2 * p][0], b[2 * p][1],
                        b[2 * p + 1][0], b[2 * p + 1][1], bd);
            }
            // P3: a_hi * b_lo
#pragma unroll
            for (int mi = 0; mi < 2; mi++)
#pragma unroll
                for (int nj = 0; nj < 4; nj++)
                    MMA16816(acc[mi][nj], a_hi[mi], b[nj]);
        }
        asm volatile("cp.async.wait_group 1;");
        __syncthreads();
    }
#undef LOADC2

    // ---- Moebius epilogue ----
    const float e = eta[0];
    float bb2[4][2];
#pragma unroll
    for (int nj = 0; nj < 4; nj++) {
        int cc = colbase + wn + nj * 8 + 2 * tig;
        bb2[nj][0] = b2[cc] * e;
        bb2[nj][1] = b2[cc + 1] * e;
    }
    const int d0c = colbase >> 4;           // blockIdx.x * 4
    const int dbloc = wn >> 4;              // 0 or 2
    float* s_out = reinterpret_cast<float*>(smem);   // 128 x 9 floats

#pragma unroll
    for (int mi = 0; mi < 2; mi++)
#pragma unroll
        for (int rsel = 0; rsel < 2; rsel++) {
            int rloc = wm + mi * 16 + g + rsel * 8;
            int grow = blockRow + rloc;
#pragma unroll
            for (int dj = 0; dj < 2; dj++) {
                int dl = dbloc + dj;        // 0..3 within CTA
                int d = d0c + dl;
                float th = theta[grow * DH + d];
                float rr = r_in[grow * DH + d];
                float sn, cs;
                sincosf(th, &sn, &cs);
                float z0 = rr * cs, z1 = rr * sn;
                float rr2 = rr * rr;
                float sumT = 0.0f, sumS = 0.0f;
#pragma unroll
                for (int hf = 0; hf < 2; hf++) {
                    int nj = 2 * dj + hf;
                    float p0 = acc[mi][nj][rsel * 2 + 0] + bb2[nj][0];
                    float p1 = acc[mi][nj][rsel * 2 + 1] + bb2[nj][1];
                    float nrm = sqrtf(p0 * p0 + p1 * p1);
                    float f = rr * 0.99f / (1.0f + nrm);
                    float w0 = f * p0, w1 = f * p1;
                    float zw0 = z0 - w0, zw1 = z1 - w1;
                    float dist2 = zw0 * zw0 + zw1 * zw1;
                    float scale = (rr2 - (w0 * w0 + w1 * w1)) / dist2;
                    float zo0 = scale * zw0 - w0;
                    float zo1 = scale * zw1 - w1;
                    float ang = atan2f(zo1, zo0);
                    if (ang < 0.0f) ang += TWO_PI_F;
                    sumT += ang;
                    sumS += scale;
                }
                sumT += __shfl_xor_sync(0xffffffffu, sumT, 1);
                sumS += __shfl_xor_sync(0xffffffffu, sumS, 1);
                sumT += __shfl_xor_sync(0xffffffffu, sumT, 2);
                sumS += __shfl_xor_sync(0xffffffffu, sumS, 2);
                if (tig == 0) {
                    s_out[rloc * 9 + dl] = sumT * 0.125f;
                    s_out[rloc * 9 + 4 + dl] = logf(sumS * 0.125f + 1e-8f);
                }
            }
        }
    __syncthreads();
#pragma unroll
    for (int it = 0; it < 4; it++) {
        int idx = tid + it * 256;           // 1024 = 128 rows x 2 tensors x 4 d
        int row = idx >> 3;
        int rest = idx & 7;
        int t = rest >> 2;
        int dl = rest & 3;
        float v = s_out[row * 9 + t * 4 + dl];
        out[(size_t)t * B_TOTAL * DH + (size_t)(blockRow + row) * DH +
            d0c + dl] = v;
    }
}

// ---------------- launch ----------------
extern "C" void kernel_launch(void* const* d_in, const int* in_sizes, int n_in,
                              void* d_out, int out_size) {
    const float* theta = (const float*)d_in[0];
    const float* r     = (const float*)d_in[1];
    const float* x     = (const float*)d_in[2];
    const float* W1    = (const float*)d_in[3];
    const float* b1    = (const float*)d_in[4];
    const float* W2    = (const float*)d_in[5];
    const float* b2    = (const float*)d_in[6];
    const float* eta   = (const float*)d_in[7];
    float* out = (float*)d_out;

    pack_all_kernel<<<8192 + 32 + 256, 256>>>(x, W1, W2, eta);

    const int smem1 = 128 * 272 * 2;     // 69632 B (>= 2x32KB chunks + staging)
    const int smem2 = 3 * 24576;         // 73728 B, 3 CTAs/SM
    cudaFuncSetAttribute(mma_phase1_kernel,
                         cudaFuncAttributeMaxDynamicSharedMemorySize, smem1);
    cudaFuncSetAttribute(mma_phase2_kernel,
                         cudaFuncAttributeMaxDynamicSharedMemorySize, smem2);

    dim3 grid1(4, B_TOTAL / 128);
    dim3 grid2(8, B_TOTAL / 128);
    mma_phase1_kernel<<<grid1, 256, smem1>>>(b1);
    mma_phase2_kernel<<<grid2, 256, smem2>>>(b2, theta, r, eta, out);
}